// round 12
// baseline (speedup 1.0000x reference)
#include <cuda_runtime.h>
#include <math.h>

#define B   16
#define Hh  128
#define Ww  128
#define CI  64
#define CO  64
#define MD  16
#define THETA 0.04908738521234052f   // 2*pi/128

typedef unsigned long long u64;

__device__ __forceinline__ u64 pk(float lo, float hi) {
    u64 r; asm("mov.b64 %0, {%1,%2};" : "=l"(r) : "f"(lo), "f"(hi)); return r;
}
__device__ __forceinline__ u64 fma2(u64 a, u64 b, u64 c) {
    u64 d; asm("fma.rn.f32x2 %0, %1, %2, %3;" : "=l"(d) : "l"(a), "l"(b), "l"(c)); return d;
}
__device__ __forceinline__ u64 add2(u64 a, u64 b) {
    u64 d; asm("add.rn.f32x2 %0, %1, %2;" : "=l"(d) : "l"(a), "l"(b)); return d;
}
#define SGN2 0x8000000080000000ULL

// ---- scratch (device globals; allocation-free). 16B aligned ----
static __device__ __align__(16) float g_Ax[B*MD*Hh*CI];     // [b][kx][h][i]
static __device__ __align__(16) float g_Ay[B*MD*Hh*CI];
static __device__ __align__(16) float g_Xx[MD*MD*B*CI];     // [m][b][i]
static __device__ __align__(16) float g_Xy[MD*MD*B*CI];
static __device__ __align__(16) float g_Wr[MD*MD*CI*CO];    // [m][i*64+o]
static __device__ __align__(16) float g_Wi[MD*MD*CI*CO];
static __device__ __align__(16) float g_Ox[B*MD*MD*CO];     // [b][kx][ky][o]
static __device__ __align__(16) float g_Oy[B*MD*MD*CO];
static __device__ __align__(16) float g_Gx[B*Hh*MD*CO];     // [b][h][kx][o]
static __device__ __align__(16) float g_Gy[B*Hh*MD*CO];

// ============ fused stage A v5 (radix-2, i-quad LDS.128) + weight transpose ============
// blocks [0,1024): A (b, h-pair). blocks [1024,2048): transpose tiles.
__global__ void __launch_bounds__(128) fusedAT(const float* __restrict__ x,
                                               const float* __restrict__ wr,
                                               const float* __restrict__ wi) {
    // pool[row 2][par 2][wl 32][i 64] = 8192 floats (32 KB)
    __shared__ __align__(16) float pool[8192];
    __shared__ __align__(16) u64 sbc[128];
    __shared__ __align__(16) u64 sbs[128];
    int tid = threadIdx.x;

    if (blockIdx.x >= 1024) {
        // ---- weight transpose tile: 32 m x 32 io (128 threads) ----
        int t   = blockIdx.x - 1024;
        int bm  = t & 7;
        int bio = t >> 3;
        int tx  = tid & 31;
        int ty  = tid >> 5;                 // 0..3
        float* sr = pool;                   // [32][33]
        float* si = pool + 1056;
#pragma unroll
        for (int r = 0; r < 8; ++r) {
            int iol = ty + r * 4;
            size_t g = (size_t)(bio * 32 + iol) * 256 + bm * 32 + tx;
            sr[iol * 33 + tx] = wr[g];
            si[iol * 33 + tx] = wi[g];
        }
        __syncthreads();
#pragma unroll
        for (int r = 0; r < 8; ++r) {
            int ml = ty + r * 4;
            size_t dst = (size_t)(bm * 32 + ml) * 4096 + bio * 32 + tx;
            g_Wr[dst] = sr[tx * 33 + ml];
            g_Wi[dst] = si[tx * 33 + ml];
        }
        return;
    }

    // ---- stage A: A[kx] = sum_{w'<64} u_{par(kx)}[w'] e^{-i kx w' th} ----
    {
        float s, c;
        sincosf((float)tid * THETA, &s, &c);
        sbc[tid] = pk(c, c);
        sbs[tid] = pk(s, s);
    }
    int b  = blockIdx.x >> 6;
    int hp = blockIdx.x & 63;
    int h0 = hp * 2;
    int iq = tid & 15, kq = tid >> 4;      // 16 i-quads x 8 kq
    int i0 = 4 * iq;
    int kxa = kq, kxb = kq + 8;            // same parity
    int du = (kq & 1) * 2048;              // odd kx -> um region
    u64 reA[2][2], imA[2][2], reB2[2][2], imB2[2][2];   // [row][comp]
#pragma unroll
    for (int r = 0; r < 2; ++r)
#pragma unroll
        for (int c = 0; c < 2; ++c) { reA[r][c]=0; imA[r][c]=0; reB2[r][c]=0; imB2[r][c]=0; }

    for (int wc = 0; wc < 2; ++wc) {
        __syncthreads();
#pragma unroll
        for (int r = 0; r < 2; ++r) {
            const ulonglong2* src = (const ulonglong2*)(x + ((size_t)(b * Hh + h0 + r) * Ww + wc * 32) * CI);
            ulonglong2* dp = (ulonglong2*)&pool[r * 4096];
            ulonglong2* dm = (ulonglong2*)&pool[r * 4096 + 2048];
            for (int l = tid; l < 512; l += 128) {
                ulonglong2 a = src[l];            // x[w']
                ulonglong2 c = src[l + 1024];     // x[w'+64]
                ulonglong2 p, m;
                p.x = add2(a.x, c.x);         p.y = add2(a.y, c.y);
                m.x = add2(a.x, c.x ^ SGN2);  m.y = add2(a.y, c.y ^ SGN2);
                dp[l] = p;
                dm[l] = m;
            }
        }
        __syncthreads();
        int ida = (kxa * (wc * 32)) & 127;
        int idb = (kxb * (wc * 32)) & 127;
#pragma unroll 8
        for (int wl = 0; wl < 32; ++wl) {
            ulonglong2 v0 = *(const ulonglong2*)&pool[du + wl * 64 + i0];
            ulonglong2 v1 = *(const ulonglong2*)&pool[4096 + du + wl * 64 + i0];
            u64 ca = sbc[ida], sa = sbs[ida];
            u64 cb = sbc[idb], sb = sbs[idb];
            ida = (ida + kxa) & 127;
            idb = (idb + kxb) & 127;
            reA[0][0]  = fma2(v0.x, ca, reA[0][0]);   reA[0][1]  = fma2(v0.y, ca, reA[0][1]);
            imA[0][0]  = fma2(v0.x, sa, imA[0][0]);   imA[0][1]  = fma2(v0.y, sa, imA[0][1]);
            reA[1][0]  = fma2(v1.x, ca, reA[1][0]);   reA[1][1]  = fma2(v1.y, ca, reA[1][1]);
            imA[1][0]  = fma2(v1.x, sa, imA[1][0]);   imA[1][1]  = fma2(v1.y, sa, imA[1][1]);
            reB2[0][0] = fma2(v0.x, cb, reB2[0][0]);  reB2[0][1] = fma2(v0.y, cb, reB2[0][1]);
            imB2[0][0] = fma2(v0.x, sb, imB2[0][0]);  imB2[0][1] = fma2(v0.y, sb, imB2[0][1]);
            reB2[1][0] = fma2(v1.x, cb, reB2[1][0]);  reB2[1][1] = fma2(v1.y, cb, reB2[1][1]);
            imB2[1][0] = fma2(v1.x, sb, imB2[1][0]);  imB2[1][1] = fma2(v1.y, sb, imB2[1][1]);
        }
    }
#pragma unroll
    for (int r = 0; r < 2; ++r) {
        size_t baseA = ((size_t)(b * MD + kxa) * Hh + h0 + r) * CI;
        size_t baseB = ((size_t)(b * MD + kxb) * Hh + h0 + r) * CI;
        ulonglong2 t;
        t.x = reA[r][0];          t.y = reA[r][1];
        *(ulonglong2*)&g_Ax[baseA + i0] = t;
        t.x = imA[r][0] ^ SGN2;   t.y = imA[r][1] ^ SGN2;     // im = -sum v*s
        *(ulonglong2*)&g_Ay[baseA + i0] = t;
        t.x = reB2[r][0];         t.y = reB2[r][1];
        *(ulonglong2*)&g_Ax[baseB + i0] = t;
        t.x = imB2[r][0] ^ SGN2;  t.y = imB2[r][1] ^ SGN2;
        *(ulonglong2*)&g_Ay[baseB + i0] = t;
    }
}

// ============ stage B v3 (radix-2, i-quad LDS.128): X[m][b][i] = sum_h A e^{-i ky h th} ============
__global__ void __launch_bounds__(128) stageB() {
    __shared__ __align__(16) float bxp[32 * 64];   // u+ (re) 8 KB
    __shared__ __align__(16) float bxm[32 * 64];   // u- (re)
    __shared__ __align__(16) float byp[32 * 64];   // u+ (im)
    __shared__ __align__(16) float bym[32 * 64];   // u- (im)
    __shared__ __align__(16) u64 sbc[128];
    __shared__ __align__(16) u64 sbs[128];
    int b  = blockIdx.x >> 4;
    int kx = blockIdx.x & 15;
    int tid = threadIdx.x;
    {
        float s, c;
        sincosf((float)tid * THETA, &s, &c);
        sbc[tid] = pk(c, c);
        sbs[tid] = pk(s, s);
    }
    int iq = tid & 15, kyg = tid >> 4;     // 16 i-quads x 8 kyg
    int i0 = 4 * iq;
    int ky0 = kyg, ky1 = kyg + 8;          // same parity
    int par = kyg & 1;
    u64 P0x=0,P0y=0,Q0x=0,Q0y=0,R0x=0,R0y=0,S0x=0,S0y=0;
    u64 P1x=0,P1y=0,Q1x=0,Q1y=0,R1x=0,R1y=0,S1x=0,S1y=0;
    const ulonglong2* Abx = (const ulonglong2*)(g_Ax + (size_t)(b * MD + kx) * Hh * CI);
    const ulonglong2* Aby = (const ulonglong2*)(g_Ay + (size_t)(b * MD + kx) * Hh * CI);

    for (int hc = 0; hc < 2; ++hc) {
        __syncthreads();
        for (int l = tid; l < 512; l += 128) {
            int row = l >> 4, q = l & 15;
            int glo = (hc * 32 + row) * 16 + q;
            int ghi = (hc * 32 + row + 64) * 16 + q;
            ulonglong2 ax = Abx[glo], cx = Abx[ghi];
            ulonglong2 ay = Aby[glo], cy = Aby[ghi];
            ulonglong2 t;
            t.x = add2(ax.x, cx.x);        t.y = add2(ax.y, cx.y);
            ((ulonglong2*)bxp)[l] = t;
            t.x = add2(ax.x, cx.x ^ SGN2); t.y = add2(ax.y, cx.y ^ SGN2);
            ((ulonglong2*)bxm)[l] = t;
            t.x = add2(ay.x, cy.x);        t.y = add2(ay.y, cy.y);
            ((ulonglong2*)byp)[l] = t;
            t.x = add2(ay.x, cy.x ^ SGN2); t.y = add2(ay.y, cy.y ^ SGN2);
            ((ulonglong2*)bym)[l] = t;
        }
        __syncthreads();
        const float* bx = par ? bxm : bxp;
        const float* by = par ? bym : byp;
        int idx0 = (ky0 * (hc * 32)) & 127;
        int idx1 = (ky1 * (hc * 32)) & 127;
#pragma unroll 8
        for (int hl = 0; hl < 32; ++hl) {
            ulonglong2 ar = *(const ulonglong2*)&bx[hl * 64 + i0];
            ulonglong2 ai = *(const ulonglong2*)&by[hl * 64 + i0];
            u64 cc0 = sbc[idx0], ss0 = sbs[idx0];
            u64 cc1 = sbc[idx1], ss1 = sbs[idx1];
            idx0 = (idx0 + ky0) & 127;
            idx1 = (idx1 + ky1) & 127;
            P0x = fma2(ar.x, cc0, P0x);  P0y = fma2(ar.y, cc0, P0y);
            Q0x = fma2(ai.x, ss0, Q0x);  Q0y = fma2(ai.y, ss0, Q0y);
            R0x = fma2(ai.x, cc0, R0x);  R0y = fma2(ai.y, cc0, R0y);
            S0x = fma2(ar.x, ss0, S0x);  S0y = fma2(ar.y, ss0, S0y);
            P1x = fma2(ar.x, cc1, P1x);  P1y = fma2(ar.y, cc1, P1y);
            Q1x = fma2(ai.x, ss1, Q1x);  Q1y = fma2(ai.y, ss1, Q1y);
            R1x = fma2(ai.x, cc1, R1x);  R1y = fma2(ai.y, cc1, R1y);
            S1x = fma2(ar.x, ss1, S1x);  S1y = fma2(ar.y, ss1, S1y);
        }
    }
    // re = P + Q ; im = R - S
    size_t b0 = ((size_t)(ky0 * MD + kx) * B + b) * CI;
    size_t b1 = ((size_t)(ky1 * MD + kx) * B + b) * CI;
    ulonglong2 t;
    t.x = add2(P0x, Q0x);         t.y = add2(P0y, Q0y);
    *(ulonglong2*)&g_Xx[b0 + i0] = t;
    t.x = add2(R0x, S0x ^ SGN2);  t.y = add2(R0y, S0y ^ SGN2);
    *(ulonglong2*)&g_Xy[b0 + i0] = t;
    t.x = add2(P1x, Q1x);         t.y = add2(P1y, Q1y);
    *(ulonglong2*)&g_Xx[b1 + i0] = t;
    t.x = add2(R1x, S1x ^ SGN2);  t.y = add2(R1y, S1y ^ SGN2);
    *(ulonglong2*)&g_Xy[b1 + i0] = t;
}

// ============ stage C: O[b][kx][ky][o] = sum_i X[m][b][i]*W[m][i][o] ============
__global__ void __launch_bounds__(256) stageC() {
    __shared__ __align__(16) float sWr[CI * CO];
    __shared__ __align__(16) float sWi[CI * CO];
    __shared__ __align__(16) u64 sXx[B * CI];
    __shared__ __align__(16) u64 sXn[B * CI];
    int m = blockIdx.x;
    int kx = m & 15, ky = m >> 4;
    int tid = threadIdx.x;
    const float4* Wr4 = (const float4*)(g_Wr + (size_t)m * 4096);
    const float4* Wi4 = (const float4*)(g_Wi + (size_t)m * 4096);
    for (int l = tid; l < 1024; l += 256) {
        ((float4*)sWr)[l] = Wr4[l];
        ((float4*)sWi)[l] = Wi4[l];
    }
    for (int l = tid; l < 1024; l += 256) {
        float vx = g_Xx[m * 1024 + l];
        float vy = g_Xy[m * 1024 + l];
        sXx[l] = pk(vx, vx);
        sXn[l] = pk(-vy, -vy);
    }
    __syncthreads();
    int oq = tid & 15;
    int b  = tid >> 4;
    u64 P0=0,P1=0,Q0=0,Q1=0,R0=0,R1=0,S0=0,S1=0;
    const u64* xp = &sXx[b * 64];
    const u64* np = &sXn[b * 64];
#pragma unroll 8
    for (int i = 0; i < CI; ++i) {
        ulonglong2 wr2 = *(const ulonglong2*)&sWr[i * 64 + 4 * oq];
        ulonglong2 wi2 = *(const ulonglong2*)&sWi[i * 64 + 4 * oq];
        u64 xv = xp[i], nv = np[i];
        P0 = fma2(xv, wr2.x, P0);  P1 = fma2(xv, wr2.y, P1);
        Q0 = fma2(nv, wi2.x, Q0);  Q1 = fma2(nv, wi2.y, Q1);
        R0 = fma2(xv, wi2.x, R0);  R1 = fma2(xv, wi2.y, R1);
        S0 = fma2(nv, wr2.x, S0);  S1 = fma2(nv, wr2.y, S1);
    }
    size_t base = ((size_t)(b * MD + kx) * MD + ky) * CO + 4 * oq;
    *(u64*)&g_Ox[base    ] = add2(P0, Q0);
    *(u64*)&g_Ox[base + 2] = add2(P1, Q1);
    *(u64*)&g_Oy[base    ] = add2(R0, S0 ^ SGN2);
    *(u64*)&g_Oy[base + 2] = add2(R1, S1 ^ SGN2);
}

// ============ stage D (radix-2): G[h'] = Se+So, G[h'+64] = Se-So ============
__global__ void __launch_bounds__(256, 4) stageD() {
    __shared__ __align__(16) float sOx[MD * CO];
    __shared__ __align__(16) float sOy[MD * CO];
    __shared__ __align__(16) u64 sTc[MD * 32];   // [ky][hl] hl<32
    __shared__ __align__(16) u64 sTs[MD * 32];
    int half = blockIdx.x & 1;
    int kx   = (blockIdx.x >> 1) & 15;
    int b    = blockIdx.x >> 5;
    int hb   = half * 32;                        // h' base (h' < 64)
    int tid  = threadIdx.x;
    for (int l = tid; l < 512; l += 256) {
        int ky = l >> 5, hl = l & 31;
        float s, c;
        sincosf((float)((ky * (hb + hl)) & 127) * THETA, &s, &c);
        sTc[l] = pk(c, c);
        sTs[l] = pk(s, s);
    }
    const float* Osx = g_Ox + (size_t)(b * MD + kx) * MD * CO;
    const float* Osy = g_Oy + (size_t)(b * MD + kx) * MD * CO;
    for (int l = tid; l < 256; l += 256) {
        ((float4*)sOx)[l] = ((const float4*)Osx)[l];
        ((float4*)sOy)[l] = ((const float4*)Osy)[l];
    }
    __syncthreads();

    int oq = tid & 15;    // o = 4*oq (2 pairs)
    int hg = tid >> 4;    // h' = hb + 2*hg + j
    u64 reE[2][2]={{0,0},{0,0}}, imE[2][2]={{0,0},{0,0}};
    u64 reO[2][2]={{0,0},{0,0}}, imO[2][2]={{0,0},{0,0}};
#pragma unroll
    for (int ky = 0; ky < MD; ++ky) {
        ulonglong2 vx = *(const ulonglong2*)&sOx[ky * 64 + 4 * oq];
        ulonglong2 vy = *(const ulonglong2*)&sOy[ky * 64 + 4 * oq];
        u64 vy0n = vy.x ^ SGN2;
        u64 vy1n = vy.y ^ SGN2;
#pragma unroll
        for (int j = 0; j < 2; ++j) {
            int hl = hg * 2 + j;
            u64 cc = sTc[ky * 32 + hl];
            u64 ss = sTs[ky * 32 + hl];
            if ((ky & 1) == 0) {
                reE[j][0] = fma2(vx.x, cc, reE[j][0]);  reE[j][0] = fma2(vy0n, ss, reE[j][0]);
                reE[j][1] = fma2(vx.y, cc, reE[j][1]);  reE[j][1] = fma2(vy1n, ss, reE[j][1]);
                imE[j][0] = fma2(vx.x, ss, imE[j][0]);  imE[j][0] = fma2(vy.x, cc, imE[j][0]);
                imE[j][1] = fma2(vx.y, ss, imE[j][1]);  imE[j][1] = fma2(vy.y, cc, imE[j][1]);
            } else {
                reO[j][0] = fma2(vx.x, cc, reO[j][0]);  reO[j][0] = fma2(vy0n, ss, reO[j][0]);
                reO[j][1] = fma2(vx.y, cc, reO[j][1]);  reO[j][1] = fma2(vy1n, ss, reO[j][1]);
                imO[j][0] = fma2(vx.x, ss, imO[j][0]);  imO[j][0] = fma2(vy.x, cc, imO[j][0]);
                imO[j][1] = fma2(vx.y, ss, imO[j][1]);  imO[j][1] = fma2(vy.y, cc, imO[j][1]);
            }
        }
    }
#pragma unroll
    for (int j = 0; j < 2; ++j) {
        int h = hb + hg * 2 + j;
        size_t b0 = ((size_t)(b * Hh + h     ) * MD + kx) * CO + 4 * oq;
        size_t b1 = ((size_t)(b * Hh + h + 64) * MD + kx) * CO + 4 * oq;
        *(u64*)&g_Gx[b0    ] = add2(reE[j][0], reO[j][0]);
        *(u64*)&g_Gx[b0 + 2] = add2(reE[j][1], reO[j][1]);
        *(u64*)&g_Gy[b0    ] = add2(imE[j][0], imO[j][0]);
        *(u64*)&g_Gy[b0 + 2] = add2(imE[j][1], imO[j][1]);
        *(u64*)&g_Gx[b1    ] = add2(reE[j][0], reO[j][0] ^ SGN2);
        *(u64*)&g_Gx[b1 + 2] = add2(reE[j][1], reO[j][1] ^ SGN2);
        *(u64*)&g_Gy[b1    ] = add2(imE[j][0], imO[j][0] ^ SGN2);
        *(u64*)&g_Gy[b1 + 2] = add2(imE[j][1], imO[j][1] ^ SGN2);
    }
}

// ============ stage E (radix-2): y[w'] = Se+So, y[w'+64] = Se-So ============
#define YPAD 66
__global__ void __launch_bounds__(128) stageE(float* __restrict__ y) {
    __shared__ __align__(16) float sGx[MD * CO];
    __shared__ __align__(16) float sGy[MD * CO];
    __shared__ __align__(16) float sY [Ww * YPAD];
    __shared__ __align__(16) u64 sEc[128];
    __shared__ __align__(16) u64 sEs[128];
    int b = blockIdx.x >> 7, h = blockIdx.x & 127;
    int tid = threadIdx.x;
    const float SC = 1.0f / 16384.0f;
    {
        float s, c;
        sincosf((float)tid * THETA, &s, &c);
        sEc[tid] = pk(2.0f * SC * c, 2.0f * SC * c);
        sEs[tid] = pk(-2.0f * SC * s, -2.0f * SC * s);
    }
    const float4* Gxs = (const float4*)&g_Gx[(size_t)(b * Hh + h) * MD * CO];
    const float4* Gys = (const float4*)&g_Gy[(size_t)(b * Hh + h) * MD * CO];
    for (int l = tid; l < MD * CO / 4; l += 128) {
        ((float4*)sGx)[l] = Gxs[l];
        ((float4*)sGy)[l] = Gys[l];
    }
    __syncthreads();
    int wl   = tid & 63;      // w' < 64
    int ohf  = tid >> 6;      // o-half
    u64 tc[16], ts[16];
    tc[0] = pk(SC, SC);  ts[0] = 0;
#pragma unroll
    for (int kx = 1; kx < MD; ++kx) {
        int idx = (kx * wl) & 127;
        tc[kx] = sEc[idx];
        ts[kx] = sEs[idx];
    }

#pragma unroll 2
    for (int oq = 0; oq < 8; ++oq) {
        int oc = (ohf * 8 + oq) * 4;     // o base (4 floats)
        u64 ae01 = 0, ae23 = 0, ao01 = 0, ao23 = 0;
#pragma unroll
        for (int kx = 0; kx < MD; ++kx) {
            ulonglong2 vx = *(const ulonglong2*)&sGx[kx * 64 + oc];
            ulonglong2 vy = *(const ulonglong2*)&sGy[kx * 64 + oc];
            if ((kx & 1) == 0) {
                ae01 = fma2(vx.x, tc[kx], ae01);  ae01 = fma2(vy.x, ts[kx], ae01);
                ae23 = fma2(vx.y, tc[kx], ae23);  ae23 = fma2(vy.y, ts[kx], ae23);
            } else {
                ao01 = fma2(vx.x, tc[kx], ao01);  ao01 = fma2(vy.x, ts[kx], ao01);
                ao23 = fma2(vx.y, tc[kx], ao23);  ao23 = fma2(vy.y, ts[kx], ao23);
            }
        }
        *(u64*)&sY[ wl       * YPAD + oc    ] = add2(ae01, ao01);
        *(u64*)&sY[ wl       * YPAD + oc + 2] = add2(ae23, ao23);
        *(u64*)&sY[(wl + 64) * YPAD + oc    ] = add2(ae01, ao01 ^ SGN2);
        *(u64*)&sY[(wl + 64) * YPAD + oc + 2] = add2(ae23, ao23 ^ SGN2);
    }
    __syncthreads();
    float* yb = y + (size_t)(b * Hh + h) * Ww * CO;
    for (int l = tid; l < Ww * CO / 2; l += 128) {
        int idx = l * 2;
        int ww = idx >> 6, o = idx & 63;
        *(u64*)&yb[idx] = *(const u64*)&sY[ww * YPAD + o];
    }
}

extern "C" void kernel_launch(void* const* d_in, const int* in_sizes, int n_in,
                              void* d_out, int out_size) {
    const float* x  = (const float*)d_in[0];
    const float* wr = (const float*)d_in[1];
    const float* wi = (const float*)d_in[2];
    float* y = (float*)d_out;

    fusedAT<<<2048, 128>>>(x, wr, wi);   // 1024 A-blocks + 1024 transpose blocks
    stageB<<<B * MD, 128>>>();
    stageC<<<MD * MD, 256>>>();
    stageD<<<B * MD * 2, 256>>>();
    stageE<<<B * Hh, 128>>>(y);
}

// round 13
// speedup vs baseline: 1.0145x; 1.0145x over previous
#include <cuda_runtime.h>
#include <math.h>

#define B   16
#define Hh  128
#define Ww  128
#define CI  64
#define CO  64
#define MD  16
#define THETA 0.04908738521234052f   // 2*pi/128

typedef unsigned long long u64;

__device__ __forceinline__ u64 pk(float lo, float hi) {
    u64 r; asm("mov.b64 %0, {%1,%2};" : "=l"(r) : "f"(lo), "f"(hi)); return r;
}
__device__ __forceinline__ u64 fma2(u64 a, u64 b, u64 c) {
    u64 d; asm("fma.rn.f32x2 %0, %1, %2, %3;" : "=l"(d) : "l"(a), "l"(b), "l"(c)); return d;
}
__device__ __forceinline__ u64 add2(u64 a, u64 b) {
    u64 d; asm("add.rn.f32x2 %0, %1, %2;" : "=l"(d) : "l"(a), "l"(b)); return d;
}
#define SGN2 0x8000000080000000ULL

// ---- scratch (device globals; allocation-free). 16B aligned ----
static __device__ __align__(16) float g_Ax[B*MD*Hh*CI];     // [b][kx][h][i]
static __device__ __align__(16) float g_Ay[B*MD*Hh*CI];
static __device__ __align__(16) float g_Xx[MD*MD*B*CI];     // [m][b][i]
static __device__ __align__(16) float g_Xy[MD*MD*B*CI];
static __device__ __align__(16) float g_Wr[MD*MD*CI*CO];    // [m][i*64+o]
static __device__ __align__(16) float g_Wi[MD*MD*CI*CO];
static __device__ __align__(16) float g_Ox[B*MD*MD*CO];     // [b][kx][ky][o]
static __device__ __align__(16) float g_Oy[B*MD*MD*CO];
static __device__ __align__(16) float g_Gx[B*Hh*MD*CO];     // [b][h][kx][o]
static __device__ __align__(16) float g_Gy[B*Hh*MD*CO];

// ============ fused stage A v4 (radix-2) + weight transpose ============
// blocks [0,1024): A (b, h-pair). blocks [1024,2048): transpose tiles.
__global__ void __launch_bounds__(256) fusedAT(const float* __restrict__ x,
                                               const float* __restrict__ wr,
                                               const float* __restrict__ wi) {
    // A: pool[row 2][par 2][wl 32][i 64] = 8192 floats (32 KB); T: aliased transpose tiles
    __shared__ __align__(16) float pool[8192];
    __shared__ __align__(16) u64 sbc[128];
    __shared__ __align__(16) u64 sbs[128];
    int tid = threadIdx.x;

    if (blockIdx.x >= 1024) {
        // ---- weight transpose tile: 32 m x 32 io ----
        int t   = blockIdx.x - 1024;
        int bm  = t & 7;
        int bio = t >> 3;
        int tx  = tid & 31;
        int ty  = tid >> 5;                 // 0..7
        float* sr = pool;                   // [32][33]
        float* si = pool + 1056;
#pragma unroll
        for (int r = 0; r < 4; ++r) {
            int iol = ty + r * 8;
            size_t g = (size_t)(bio * 32 + iol) * 256 + bm * 32 + tx;
            sr[iol * 33 + tx] = wr[g];
            si[iol * 33 + tx] = wi[g];
        }
        __syncthreads();
#pragma unroll
        for (int r = 0; r < 4; ++r) {
            int ml = ty + r * 8;
            size_t dst = (size_t)(bm * 32 + ml) * 4096 + bio * 32 + tx;
            g_Wr[dst] = sr[tx * 33 + ml];
            g_Wi[dst] = si[tx * 33 + ml];
        }
        return;
    }

    // ---- stage A: A[kx] = sum_{w'<64} u_{par(kx)}[w'] e^{-i kx w' th} ----
    if (tid < 128) {
        float s, c;
        sincosf((float)tid * THETA, &s, &c);
        sbc[tid] = pk(c, c);
        sbs[tid] = pk(s, s);
    }
    int b  = blockIdx.x >> 6;
    int hp = blockIdx.x & 63;
    int h0 = hp * 2;
    int ipair = tid & 31, kq = tid >> 5;   // kx = kq, kq+8 (same parity); warp-uniform kq
    int i0 = 2 * ipair;
    int kxa = kq, kxb = kq + 8;
    int du = (kq & 1) * 2048;              // odd kx -> um region
    u64 reA0=0, imA0=0, reB0=0, imB0=0;    // row0: kxa, kxb
    u64 reA1=0, imA1=0, reB1=0, imB1=0;    // row1

    for (int wc = 0; wc < 2; ++wc) {
        __syncthreads();
#pragma unroll
        for (int r = 0; r < 2; ++r) {
            const ulonglong2* src = (const ulonglong2*)(x + ((size_t)(b * Hh + h0 + r) * Ww + wc * 32) * CI);
            ulonglong2* dp = (ulonglong2*)&pool[r * 4096];
            ulonglong2* dm = (ulonglong2*)&pool[r * 4096 + 2048];
            for (int l = tid; l < 512; l += 256) {
                ulonglong2 a = src[l];            // x[w']
                ulonglong2 c = src[l + 1024];     // x[w'+64]
                ulonglong2 p, m;
                p.x = add2(a.x, c.x);         p.y = add2(a.y, c.y);
                m.x = add2(a.x, c.x ^ SGN2);  m.y = add2(a.y, c.y ^ SGN2);
                dp[l] = p;
                dm[l] = m;
            }
        }
        __syncthreads();
        int ida = (kxa * (wc * 32)) & 127;
        int idb = (kxb * (wc * 32)) & 127;
#pragma unroll 8
        for (int wl = 0; wl < 32; ++wl) {
            u64 v0 = *(const u64*)&pool[du + wl * 64 + i0];
            u64 v1 = *(const u64*)&pool[4096 + du + wl * 64 + i0];
            u64 ca = sbc[ida], sa = sbs[ida];
            u64 cb = sbc[idb], sb = sbs[idb];
            ida = (ida + kxa) & 127;
            idb = (idb + kxb) & 127;
            reA0 = fma2(v0, ca, reA0);  imA0 = fma2(v0, sa, imA0);
            reA1 = fma2(v1, ca, reA1);  imA1 = fma2(v1, sa, imA1);
            reB0 = fma2(v0, cb, reB0);  imB0 = fma2(v0, sb, imB0);
            reB1 = fma2(v1, cb, reB1);  imB1 = fma2(v1, sb, imB1);
        }
    }
    size_t baseA0 = ((size_t)(b * MD + kxa) * Hh + h0    ) * CI;
    size_t baseA1 = ((size_t)(b * MD + kxa) * Hh + h0 + 1) * CI;
    size_t baseB0 = ((size_t)(b * MD + kxb) * Hh + h0    ) * CI;
    size_t baseB1 = ((size_t)(b * MD + kxb) * Hh + h0 + 1) * CI;
    *(u64*)&g_Ax[baseA0 + i0] = reA0;  *(u64*)&g_Ay[baseA0 + i0] = imA0 ^ SGN2;
    *(u64*)&g_Ax[baseA1 + i0] = reA1;  *(u64*)&g_Ay[baseA1 + i0] = imA1 ^ SGN2;
    *(u64*)&g_Ax[baseB0 + i0] = reB0;  *(u64*)&g_Ay[baseB0 + i0] = imB0 ^ SGN2;
    *(u64*)&g_Ax[baseB1 + i0] = reB1;  *(u64*)&g_Ay[baseB1 + i0] = imB1 ^ SGN2;
}

// ============ stage B v2 (radix-2, full i per block): X[m][b][i] = sum_h A e^{-i ky h th} ============
__global__ void __launch_bounds__(256) stageB() {
    __shared__ __align__(16) float bxp[32 * 64];   // u+ (re) 8 KB
    __shared__ __align__(16) float bxm[32 * 64];   // u- (re)
    __shared__ __align__(16) float byp[32 * 64];   // u+ (im)
    __shared__ __align__(16) float bym[32 * 64];   // u- (im)
    __shared__ __align__(16) u64 sbc[128];
    __shared__ __align__(16) u64 sbs[128];
    int b  = blockIdx.x >> 4;
    int kx = blockIdx.x & 15;
    int tid = threadIdx.x;
    if (tid < 128) {
        float s, c;
        sincosf((float)tid * THETA, &s, &c);
        sbc[tid] = pk(c, c);
        sbs[tid] = pk(s, s);
    }
    int ipair = tid & 31, kyg = tid >> 5;   // ky = kyg, kyg+8 (same parity); warp-uniform
    int i0 = 2 * ipair;
    int ky0 = kyg, ky1 = kyg + 8;
    int par = kyg & 1;
    u64 P0=0,Q0=0,R0=0,S0=0, P1=0,Q1=0,R1=0,S1=0;
    const ulonglong2* Abx = (const ulonglong2*)(g_Ax + (size_t)(b * MD + kx) * Hh * CI);
    const ulonglong2* Aby = (const ulonglong2*)(g_Ay + (size_t)(b * MD + kx) * Hh * CI);

    for (int hc = 0; hc < 2; ++hc) {
        __syncthreads();
        for (int l = tid; l < 512; l += 256) {
            int row = l >> 4, q = l & 15;
            int glo = (hc * 32 + row) * 16 + q;
            int ghi = (hc * 32 + row + 64) * 16 + q;
            ulonglong2 ax = Abx[glo], cx = Abx[ghi];
            ulonglong2 ay = Aby[glo], cy = Aby[ghi];
            ulonglong2 t;
            t.x = add2(ax.x, cx.x);        t.y = add2(ax.y, cx.y);
            ((ulonglong2*)bxp)[l] = t;
            t.x = add2(ax.x, cx.x ^ SGN2); t.y = add2(ax.y, cx.y ^ SGN2);
            ((ulonglong2*)bxm)[l] = t;
            t.x = add2(ay.x, cy.x);        t.y = add2(ay.y, cy.y);
            ((ulonglong2*)byp)[l] = t;
            t.x = add2(ay.x, cy.x ^ SGN2); t.y = add2(ay.y, cy.y ^ SGN2);
            ((ulonglong2*)bym)[l] = t;
        }
        __syncthreads();
        const float* bx = par ? bxm : bxp;
        const float* by = par ? bym : byp;
        int idx0 = (ky0 * (hc * 32)) & 127;
        int idx1 = (ky1 * (hc * 32)) & 127;
#pragma unroll 8
        for (int hl = 0; hl < 32; ++hl) {
            u64 ar = *(const u64*)&bx[hl * 64 + i0];
            u64 ai = *(const u64*)&by[hl * 64 + i0];
            u64 cc0 = sbc[idx0], ss0 = sbs[idx0];
            u64 cc1 = sbc[idx1], ss1 = sbs[idx1];
            idx0 = (idx0 + ky0) & 127;
            idx1 = (idx1 + ky1) & 127;
            P0 = fma2(ar, cc0, P0);  Q0 = fma2(ai, ss0, Q0);
            R0 = fma2(ai, cc0, R0);  S0 = fma2(ar, ss0, S0);
            P1 = fma2(ar, cc1, P1);  Q1 = fma2(ai, ss1, Q1);
            R1 = fma2(ai, cc1, R1);  S1 = fma2(ar, ss1, S1);
        }
    }
    // re = P + Q ; im = R - S
    size_t b0 = ((size_t)(ky0 * MD + kx) * B + b) * CI;
    size_t b1 = ((size_t)(ky1 * MD + kx) * B + b) * CI;
    *(u64*)&g_Xx[b0 + i0] = add2(P0, Q0);
    *(u64*)&g_Xy[b0 + i0] = add2(R0, S0 ^ SGN2);
    *(u64*)&g_Xx[b1 + i0] = add2(P1, Q1);
    *(u64*)&g_Xy[b1 + i0] = add2(R1, S1 ^ SGN2);
}

// ============ stage C: O[b][kx][ky][o] = sum_i X[m][b][i]*W[m][i][o] ============
__global__ void __launch_bounds__(256) stageC() {
    __shared__ __align__(16) float sWr[CI * CO];
    __shared__ __align__(16) float sWi[CI * CO];
    __shared__ __align__(16) u64 sXx[B * CI];
    __shared__ __align__(16) u64 sXn[B * CI];
    int m = blockIdx.x;
    int kx = m & 15, ky = m >> 4;
    int tid = threadIdx.x;
    const float4* Wr4 = (const float4*)(g_Wr + (size_t)m * 4096);
    const float4* Wi4 = (const float4*)(g_Wi + (size_t)m * 4096);
    for (int l = tid; l < 1024; l += 256) {
        ((float4*)sWr)[l] = Wr4[l];
        ((float4*)sWi)[l] = Wi4[l];
    }
    for (int l = tid; l < 1024; l += 256) {
        float vx = g_Xx[m * 1024 + l];
        float vy = g_Xy[m * 1024 + l];
        sXx[l] = pk(vx, vx);
        sXn[l] = pk(-vy, -vy);
    }
    __syncthreads();
    int oq = tid & 15;
    int b  = tid >> 4;
    u64 P0=0,P1=0,Q0=0,Q1=0,R0=0,R1=0,S0=0,S1=0;
    const u64* xp = &sXx[b * 64];
    const u64* np = &sXn[b * 64];
#pragma unroll 8
    for (int i = 0; i < CI; ++i) {
        ulonglong2 wr2 = *(const ulonglong2*)&sWr[i * 64 + 4 * oq];
        ulonglong2 wi2 = *(const ulonglong2*)&sWi[i * 64 + 4 * oq];
        u64 xv = xp[i], nv = np[i];
        P0 = fma2(xv, wr2.x, P0);  P1 = fma2(xv, wr2.y, P1);
        Q0 = fma2(nv, wi2.x, Q0);  Q1 = fma2(nv, wi2.y, Q1);
        R0 = fma2(xv, wi2.x, R0);  R1 = fma2(xv, wi2.y, R1);
        S0 = fma2(nv, wr2.x, S0);  S1 = fma2(nv, wr2.y, S1);
    }
    size_t base = ((size_t)(b * MD + kx) * MD + ky) * CO + 4 * oq;
    *(u64*)&g_Ox[base    ] = add2(P0, Q0);
    *(u64*)&g_Ox[base + 2] = add2(P1, Q1);
    *(u64*)&g_Oy[base    ] = add2(R0, S0 ^ SGN2);
    *(u64*)&g_Oy[base + 2] = add2(R1, S1 ^ SGN2);
}

// ============ stage D (radix-2): G[h'] = Se+So, G[h'+64] = Se-So ============
__global__ void __launch_bounds__(256, 4) stageD() {
    __shared__ __align__(16) float sOx[MD * CO];
    __shared__ __align__(16) float sOy[MD * CO];
    __shared__ __align__(16) u64 sTc[MD * 32];   // [ky][hl] hl<32
    __shared__ __align__(16) u64 sTs[MD * 32];
    int half = blockIdx.x & 1;
    int kx   = (blockIdx.x >> 1) & 15;
    int b    = blockIdx.x >> 5;
    int hb   = half * 32;                        // h' base (h' < 64)
    int tid  = threadIdx.x;
    for (int l = tid; l < 512; l += 256) {
        int ky = l >> 5, hl = l & 31;
        float s, c;
        sincosf((float)((ky * (hb + hl)) & 127) * THETA, &s, &c);
        sTc[l] = pk(c, c);
        sTs[l] = pk(s, s);
    }
    const float* Osx = g_Ox + (size_t)(b * MD + kx) * MD * CO;
    const float* Osy = g_Oy + (size_t)(b * MD + kx) * MD * CO;
    for (int l = tid; l < 256; l += 256) {
        ((float4*)sOx)[l] = ((const float4*)Osx)[l];
        ((float4*)sOy)[l] = ((const float4*)Osy)[l];
    }
    __syncthreads();

    int oq = tid & 15;    // o = 4*oq (2 pairs)
    int hg = tid >> 4;    // h' = hb + 2*hg + j
    u64 reE[2][2]={{0,0},{0,0}}, imE[2][2]={{0,0},{0,0}};
    u64 reO[2][2]={{0,0},{0,0}}, imO[2][2]={{0,0},{0,0}};
#pragma unroll
    for (int ky = 0; ky < MD; ++ky) {
        ulonglong2 vx = *(const ulonglong2*)&sOx[ky * 64 + 4 * oq];
        ulonglong2 vy = *(const ulonglong2*)&sOy[ky * 64 + 4 * oq];
        u64 vy0n = vy.x ^ SGN2;
        u64 vy1n = vy.y ^ SGN2;
#pragma unroll
        for (int j = 0; j < 2; ++j) {
            int hl = hg * 2 + j;
            u64 cc = sTc[ky * 32 + hl];
            u64 ss = sTs[ky * 32 + hl];
            if ((ky & 1) == 0) {
                reE[j][0] = fma2(vx.x, cc, reE[j][0]);  reE[j][0] = fma2(vy0n, ss, reE[j][0]);
                reE[j][1] = fma2(vx.y, cc, reE[j][1]);  reE[j][1] = fma2(vy1n, ss, reE[j][1]);
                imE[j][0] = fma2(vx.x, ss, imE[j][0]);  imE[j][0] = fma2(vy.x, cc, imE[j][0]);
                imE[j][1] = fma2(vx.y, ss, imE[j][1]);  imE[j][1] = fma2(vy.y, cc, imE[j][1]);
            } else {
                reO[j][0] = fma2(vx.x, cc, reO[j][0]);  reO[j][0] = fma2(vy0n, ss, reO[j][0]);
                reO[j][1] = fma2(vx.y, cc, reO[j][1]);  reO[j][1] = fma2(vy1n, ss, reO[j][1]);
                imO[j][0] = fma2(vx.x, ss, imO[j][0]);  imO[j][0] = fma2(vy.x, cc, imO[j][0]);
                imO[j][1] = fma2(vx.y, ss, imO[j][1]);  imO[j][1] = fma2(vy.y, cc, imO[j][1]);
            }
        }
    }
#pragma unroll
    for (int j = 0; j < 2; ++j) {
        int h = hb + hg * 2 + j;
        size_t b0 = ((size_t)(b * Hh + h     ) * MD + kx) * CO + 4 * oq;
        size_t b1 = ((size_t)(b * Hh + h + 64) * MD + kx) * CO + 4 * oq;
        *(u64*)&g_Gx[b0    ] = add2(reE[j][0], reO[j][0]);
        *(u64*)&g_Gx[b0 + 2] = add2(reE[j][1], reO[j][1]);
        *(u64*)&g_Gy[b0    ] = add2(imE[j][0], imO[j][0]);
        *(u64*)&g_Gy[b0 + 2] = add2(imE[j][1], imO[j][1]);
        *(u64*)&g_Gx[b1    ] = add2(reE[j][0], reO[j][0] ^ SGN2);
        *(u64*)&g_Gx[b1 + 2] = add2(reE[j][1], reO[j][1] ^ SGN2);
        *(u64*)&g_Gy[b1    ] = add2(imE[j][0], imO[j][0] ^ SGN2);
        *(u64*)&g_Gy[b1 + 2] = add2(imE[j][1], imO[j][1] ^ SGN2);
    }
}

// ============ stage E v2 (radix-2, 256 threads): y[w'] = Se+So, y[w'+64] = Se-So ============
#define YPAD 66
__global__ void __launch_bounds__(256) stageE(float* __restrict__ y) {
    __shared__ __align__(16) float sGx[MD * CO];
    __shared__ __align__(16) float sGy[MD * CO];
    __shared__ __align__(16) float sY [Ww * YPAD];
    __shared__ __align__(16) u64 sEc[128];
    __shared__ __align__(16) u64 sEs[128];
    int b = blockIdx.x >> 7, h = blockIdx.x & 127;
    int tid = threadIdx.x;
    const float SC = 1.0f / 16384.0f;
    if (tid < 128) {
        float s, c;
        sincosf((float)tid * THETA, &s, &c);
        sEc[tid] = pk(2.0f * SC * c, 2.0f * SC * c);
        sEs[tid] = pk(-2.0f * SC * s, -2.0f * SC * s);
    }
    const float4* Gxs = (const float4*)&g_Gx[(size_t)(b * Hh + h) * MD * CO];
    const float4* Gys = (const float4*)&g_Gy[(size_t)(b * Hh + h) * MD * CO];
    for (int l = tid; l < MD * CO / 4; l += 256) {
        ((float4*)sGx)[l] = Gxs[l];
        ((float4*)sGy)[l] = Gys[l];
    }
    __syncthreads();
    int wl = tid & 63;       // w' < 64
    int og = tid >> 6;       // o-quarter (0..3): 4 oq each
    u64 tc[16], ts[16];
    tc[0] = pk(SC, SC);  ts[0] = 0;
#pragma unroll
    for (int kx = 1; kx < MD; ++kx) {
        int idx = (kx * wl) & 127;
        tc[kx] = sEc[idx];
        ts[kx] = sEs[idx];
    }

#pragma unroll
    for (int oq = 0; oq < 4; ++oq) {
        int oc = (og * 4 + oq) * 4;      // o base (4 floats)
        u64 ae01 = 0, ae23 = 0, ao01 = 0, ao23 = 0;
#pragma unroll
        for (int kx = 0; kx < MD; ++kx) {
            ulonglong2 vx = *(const ulonglong2*)&sGx[kx * 64 + oc];
            ulonglong2 vy = *(const ulonglong2*)&sGy[kx * 64 + oc];
            if ((kx & 1) == 0) {
                ae01 = fma2(vx.x, tc[kx], ae01);  ae01 = fma2(vy.x, ts[kx], ae01);
                ae23 = fma2(vx.y, tc[kx], ae23);  ae23 = fma2(vy.y, ts[kx], ae23);
            } else {
                ao01 = fma2(vx.x, tc[kx], ao01);  ao01 = fma2(vy.x, ts[kx], ao01);
                ao23 = fma2(vx.y, tc[kx], ao23);  ao23 = fma2(vy.y, ts[kx], ao23);
            }
        }
        *(u64*)&sY[ wl       * YPAD + oc    ] = add2(ae01, ao01);
        *(u64*)&sY[ wl       * YPAD + oc + 2] = add2(ae23, ao23);
        *(u64*)&sY[(wl + 64) * YPAD + oc    ] = add2(ae01, ao01 ^ SGN2);
        *(u64*)&sY[(wl + 64) * YPAD + oc + 2] = add2(ae23, ao23 ^ SGN2);
    }
    __syncthreads();
    float* yb = y + (size_t)(b * Hh + h) * Ww * CO;
    for (int l = tid; l < Ww * CO / 2; l += 256) {
        int idx = l * 2;
        int ww = idx >> 6, o = idx & 63;
        *(u64*)&yb[idx] = *(const u64*)&sY[ww * YPAD + o];
    }
}

extern "C" void kernel_launch(void* const* d_in, const int* in_sizes, int n_in,
                              void* d_out, int out_size) {
    const float* x  = (const float*)d_in[0];
    const float* wr = (const float*)d_in[1];
    const float* wi = (const float*)d_in[2];
    float* y = (float*)d_out;

    fusedAT<<<2048, 256>>>(x, wr, wi);   // 1024 A-blocks + 1024 transpose blocks
    stageB<<<B * MD, 256>>>();
    stageC<<<MD * MD, 256>>>();
    stageD<<<B * MD * 2, 256>>>();
    stageE<<<B * Hh, 256>>>(y);
}

// round 14
// speedup vs baseline: 1.0849x; 1.0694x over previous
#include <cuda_runtime.h>
#include <math.h>

#define B   16
#define Hh  128
#define Ww  128
#define CI  64
#define CO  64
#define MD  16
#define THETA 0.04908738521234052f   // 2*pi/128

typedef unsigned long long u64;

__device__ __forceinline__ u64 pk(float lo, float hi) {
    u64 r; asm("mov.b64 %0, {%1,%2};" : "=l"(r) : "f"(lo), "f"(hi)); return r;
}
__device__ __forceinline__ u64 fma2(u64 a, u64 b, u64 c) {
    u64 d; asm("fma.rn.f32x2 %0, %1, %2, %3;" : "=l"(d) : "l"(a), "l"(b), "l"(c)); return d;
}
__device__ __forceinline__ u64 add2(u64 a, u64 b) {
    u64 d; asm("add.rn.f32x2 %0, %1, %2;" : "=l"(d) : "l"(a), "l"(b)); return d;
}
#define SGN2 0x8000000080000000ULL

// ---- scratch (device globals; allocation-free). 16B aligned ----
static __device__ __align__(16) float g_Ax[B*MD*Hh*CI];     // [b][kx][h][i]
static __device__ __align__(16) float g_Ay[B*MD*Hh*CI];
static __device__ __align__(16) float g_Xx[MD*MD*B*CI];     // [m][b][i]
static __device__ __align__(16) float g_Xy[MD*MD*B*CI];
static __device__ __align__(16) float g_Wr[MD*MD*CI*CO];    // [m][i*64+o]
static __device__ __align__(16) float g_Wi[MD*MD*CI*CO];
static __device__ __align__(16) float g_Ox[B*MD*MD*CO];     // [b][kx][ky][o]
static __device__ __align__(16) float g_Oy[B*MD*MD*CO];
static __device__ __align__(16) float g_Gx[B*Hh*MD*CO];     // [b][h][kx][o]
static __device__ __align__(16) float g_Gy[B*Hh*MD*CO];

// ============ fused stage A (radix-2, fused twiddle LDS.128) + weight transpose ============
// blocks [0,1024): A (b, h-pair). blocks [1024,2048): transpose tiles.
__global__ void __launch_bounds__(256) fusedAT(const float* __restrict__ x,
                                               const float* __restrict__ wr,
                                               const float* __restrict__ wi) {
    __shared__ __align__(16) float pool[8192];       // 32 KB
    __shared__ __align__(16) ulonglong2 sbt[128];    // {(c,c),(s,s)} 2 KB
    int tid = threadIdx.x;

    if (blockIdx.x >= 1024) {
        // ---- weight transpose tile: 32 m x 32 io ----
        int t   = blockIdx.x - 1024;
        int bm  = t & 7;
        int bio = t >> 3;
        int tx  = tid & 31;
        int ty  = tid >> 5;                 // 0..7
        float* sr = pool;                   // [32][33]
        float* si = pool + 1056;
#pragma unroll
        for (int r = 0; r < 4; ++r) {
            int iol = ty + r * 8;
            size_t g = (size_t)(bio * 32 + iol) * 256 + bm * 32 + tx;
            sr[iol * 33 + tx] = wr[g];
            si[iol * 33 + tx] = wi[g];
        }
        __syncthreads();
#pragma unroll
        for (int r = 0; r < 4; ++r) {
            int ml = ty + r * 8;
            size_t dst = (size_t)(bm * 32 + ml) * 4096 + bio * 32 + tx;
            g_Wr[dst] = sr[tx * 33 + ml];
            g_Wi[dst] = si[tx * 33 + ml];
        }
        return;
    }

    // ---- stage A: A[kx] = sum_{w'<64} u_{par(kx)}[w'] e^{-i kx w' th} ----
    if (tid < 128) {
        float s, c;
        sincosf((float)tid * THETA, &s, &c);
        ulonglong2 t;
        t.x = pk(c, c);
        t.y = pk(s, s);
        sbt[tid] = t;
    }
    int b  = blockIdx.x >> 6;
    int hp = blockIdx.x & 63;
    int h0 = hp * 2;
    int ipair = tid & 31, kq = tid >> 5;   // kx = kq, kq+8 (same parity); warp-uniform kq
    int i0 = 2 * ipair;
    int kxa = kq, kxb = kq + 8;
    int du = (kq & 1) * 2048;              // odd kx -> um region
    u64 reA0=0, imA0=0, reB0=0, imB0=0;    // row0: kxa, kxb
    u64 reA1=0, imA1=0, reB1=0, imB1=0;    // row1

    for (int wc = 0; wc < 2; ++wc) {
        __syncthreads();
#pragma unroll
        for (int r = 0; r < 2; ++r) {
            const ulonglong2* src = (const ulonglong2*)(x + ((size_t)(b * Hh + h0 + r) * Ww + wc * 32) * CI);
            ulonglong2* dp = (ulonglong2*)&pool[r * 4096];
            ulonglong2* dm = (ulonglong2*)&pool[r * 4096 + 2048];
            for (int l = tid; l < 512; l += 256) {
                ulonglong2 a = src[l];            // x[w']
                ulonglong2 c = src[l + 1024];     // x[w'+64]
                ulonglong2 p, m;
                p.x = add2(a.x, c.x);         p.y = add2(a.y, c.y);
                m.x = add2(a.x, c.x ^ SGN2);  m.y = add2(a.y, c.y ^ SGN2);
                dp[l] = p;
                dm[l] = m;
            }
        }
        __syncthreads();
        int ida = (kxa * (wc * 32)) & 127;
        int idb = (kxb * (wc * 32)) & 127;
#pragma unroll 8
        for (int wl = 0; wl < 32; ++wl) {
            u64 v0 = *(const u64*)&pool[du + wl * 64 + i0];
            u64 v1 = *(const u64*)&pool[4096 + du + wl * 64 + i0];
            ulonglong2 ta = sbt[ida];
            ulonglong2 tb = sbt[idb];
            ida = (ida + kxa) & 127;
            idb = (idb + kxb) & 127;
            reA0 = fma2(v0, ta.x, reA0);  imA0 = fma2(v0, ta.y, imA0);
            reA1 = fma2(v1, ta.x, reA1);  imA1 = fma2(v1, ta.y, imA1);
            reB0 = fma2(v0, tb.x, reB0);  imB0 = fma2(v0, tb.y, imB0);
            reB1 = fma2(v1, tb.x, reB1);  imB1 = fma2(v1, tb.y, imB1);
        }
    }
    size_t baseA0 = ((size_t)(b * MD + kxa) * Hh + h0    ) * CI;
    size_t baseA1 = ((size_t)(b * MD + kxa) * Hh + h0 + 1) * CI;
    size_t baseB0 = ((size_t)(b * MD + kxb) * Hh + h0    ) * CI;
    size_t baseB1 = ((size_t)(b * MD + kxb) * Hh + h0 + 1) * CI;
    *(u64*)&g_Ax[baseA0 + i0] = reA0;  *(u64*)&g_Ay[baseA0 + i0] = imA0 ^ SGN2;
    *(u64*)&g_Ax[baseA1 + i0] = reA1;  *(u64*)&g_Ay[baseA1 + i0] = imA1 ^ SGN2;
    *(u64*)&g_Ax[baseB0 + i0] = reB0;  *(u64*)&g_Ay[baseB0 + i0] = imB0 ^ SGN2;
    *(u64*)&g_Ax[baseB1 + i0] = reB1;  *(u64*)&g_Ay[baseB1 + i0] = imB1 ^ SGN2;
}

// ============ stage B (radix-2, fused twiddle LDS.128): X[m][b][i] = sum_h A e^{-i ky h th} ============
__global__ void __launch_bounds__(256) stageB() {
    __shared__ __align__(16) float bxp[32 * 64];   // u+ (re) 8 KB
    __shared__ __align__(16) float bxm[32 * 64];   // u- (re)
    __shared__ __align__(16) float byp[32 * 64];   // u+ (im)
    __shared__ __align__(16) float bym[32 * 64];   // u- (im)
    __shared__ __align__(16) ulonglong2 sbt[128];  // {(c,c),(s,s)}
    int b  = blockIdx.x >> 4;
    int kx = blockIdx.x & 15;
    int tid = threadIdx.x;
    if (tid < 128) {
        float s, c;
        sincosf((float)tid * THETA, &s, &c);
        ulonglong2 t;
        t.x = pk(c, c);
        t.y = pk(s, s);
        sbt[tid] = t;
    }
    int ipair = tid & 31, kyg = tid >> 5;   // ky = kyg, kyg+8 (same parity); warp-uniform
    int i0 = 2 * ipair;
    int ky0 = kyg, ky1 = kyg + 8;
    int par = kyg & 1;
    u64 P0=0,Q0=0,R0=0,S0=0, P1=0,Q1=0,R1=0,S1=0;
    const ulonglong2* Abx = (const ulonglong2*)(g_Ax + (size_t)(b * MD + kx) * Hh * CI);
    const ulonglong2* Aby = (const ulonglong2*)(g_Ay + (size_t)(b * MD + kx) * Hh * CI);

    for (int hc = 0; hc < 2; ++hc) {
        __syncthreads();
        for (int l = tid; l < 512; l += 256) {
            int row = l >> 4, q = l & 15;
            int glo = (hc * 32 + row) * 16 + q;
            int ghi = (hc * 32 + row + 64) * 16 + q;
            ulonglong2 ax = Abx[glo], cx = Abx[ghi];
            ulonglong2 ay = Aby[glo], cy = Aby[ghi];
            ulonglong2 t;
            t.x = add2(ax.x, cx.x);        t.y = add2(ax.y, cx.y);
            ((ulonglong2*)bxp)[l] = t;
            t.x = add2(ax.x, cx.x ^ SGN2); t.y = add2(ax.y, cx.y ^ SGN2);
            ((ulonglong2*)bxm)[l] = t;
            t.x = add2(ay.x, cy.x);        t.y = add2(ay.y, cy.y);
            ((ulonglong2*)byp)[l] = t;
            t.x = add2(ay.x, cy.x ^ SGN2); t.y = add2(ay.y, cy.y ^ SGN2);
            ((ulonglong2*)bym)[l] = t;
        }
        __syncthreads();
        const float* bx = par ? bxm : bxp;
        const float* by = par ? bym : byp;
        int idx0 = (ky0 * (hc * 32)) & 127;
        int idx1 = (ky1 * (hc * 32)) & 127;
#pragma unroll 8
        for (int hl = 0; hl < 32; ++hl) {
            u64 ar = *(const u64*)&bx[hl * 64 + i0];
            u64 ai = *(const u64*)&by[hl * 64 + i0];
            ulonglong2 t0 = sbt[idx0];
            ulonglong2 t1 = sbt[idx1];
            idx0 = (idx0 + ky0) & 127;
            idx1 = (idx1 + ky1) & 127;
            P0 = fma2(ar, t0.x, P0);  Q0 = fma2(ai, t0.y, Q0);
            R0 = fma2(ai, t0.x, R0);  S0 = fma2(ar, t0.y, S0);
            P1 = fma2(ar, t1.x, P1);  Q1 = fma2(ai, t1.y, Q1);
            R1 = fma2(ai, t1.x, R1);  S1 = fma2(ar, t1.y, S1);
        }
    }
    // re = P + Q ; im = R - S
    size_t b0 = ((size_t)(ky0 * MD + kx) * B + b) * CI;
    size_t b1 = ((size_t)(ky1 * MD + kx) * B + b) * CI;
    *(u64*)&g_Xx[b0 + i0] = add2(P0, Q0);
    *(u64*)&g_Xy[b0 + i0] = add2(R0, S0 ^ SGN2);
    *(u64*)&g_Xx[b1 + i0] = add2(P1, Q1);
    *(u64*)&g_Xy[b1 + i0] = add2(R1, S1 ^ SGN2);
}

// ============ stage C: O[b][kx][ky][o] = sum_i X[m][b][i]*W[m][i][o] ============
__global__ void __launch_bounds__(256) stageC() {
    __shared__ __align__(16) float sWr[CI * CO];
    __shared__ __align__(16) float sWi[CI * CO];
    __shared__ __align__(16) u64 sXx[B * CI];
    __shared__ __align__(16) u64 sXn[B * CI];
    int m = blockIdx.x;
    int kx = m & 15, ky = m >> 4;
    int tid = threadIdx.x;
    const float4* Wr4 = (const float4*)(g_Wr + (size_t)m * 4096);
    const float4* Wi4 = (const float4*)(g_Wi + (size_t)m * 4096);
    for (int l = tid; l < 1024; l += 256) {
        ((float4*)sWr)[l] = Wr4[l];
        ((float4*)sWi)[l] = Wi4[l];
    }
    for (int l = tid; l < 1024; l += 256) {
        float vx = g_Xx[m * 1024 + l];
        float vy = g_Xy[m * 1024 + l];
        sXx[l] = pk(vx, vx);
        sXn[l] = pk(-vy, -vy);
    }
    __syncthreads();
    int oq = tid & 15;
    int b  = tid >> 4;
    u64 P0=0,P1=0,Q0=0,Q1=0,R0=0,R1=0,S0=0,S1=0;
    const u64* xp = &sXx[b * 64];
    const u64* np = &sXn[b * 64];
#pragma unroll 8
    for (int i = 0; i < CI; ++i) {
        ulonglong2 wr2 = *(const ulonglong2*)&sWr[i * 64 + 4 * oq];
        ulonglong2 wi2 = *(const ulonglong2*)&sWi[i * 64 + 4 * oq];
        u64 xv = xp[i], nv = np[i];
        P0 = fma2(xv, wr2.x, P0);  P1 = fma2(xv, wr2.y, P1);
        Q0 = fma2(nv, wi2.x, Q0);  Q1 = fma2(nv, wi2.y, Q1);
        R0 = fma2(xv, wi2.x, R0);  R1 = fma2(xv, wi2.y, R1);
        S0 = fma2(nv, wr2.x, S0);  S1 = fma2(nv, wr2.y, S1);
    }
    size_t base = ((size_t)(b * MD + kx) * MD + ky) * CO + 4 * oq;
    *(u64*)&g_Ox[base    ] = add2(P0, Q0);
    *(u64*)&g_Ox[base + 2] = add2(P1, Q1);
    *(u64*)&g_Oy[base    ] = add2(R0, S0 ^ SGN2);
    *(u64*)&g_Oy[base + 2] = add2(R1, S1 ^ SGN2);
}

// ============ stage D (radix-2, fused twiddle LDS.128): G[h'] = Se+So, G[h'+64] = Se-So ============
__global__ void __launch_bounds__(256, 4) stageD() {
    __shared__ __align__(16) float sOx[MD * CO];
    __shared__ __align__(16) float sOy[MD * CO];
    __shared__ __align__(16) ulonglong2 sT[MD * 32];   // {(c,c),(s,s)} [ky][hl]
    int half = blockIdx.x & 1;
    int kx   = (blockIdx.x >> 1) & 15;
    int b    = blockIdx.x >> 5;
    int hb   = half * 32;                        // h' base (h' < 64)
    int tid  = threadIdx.x;
    for (int l = tid; l < 512; l += 256) {
        int ky = l >> 5, hl = l & 31;
        float s, c;
        sincosf((float)((ky * (hb + hl)) & 127) * THETA, &s, &c);
        ulonglong2 t;
        t.x = pk(c, c);
        t.y = pk(s, s);
        sT[l] = t;
    }
    const float* Osx = g_Ox + (size_t)(b * MD + kx) * MD * CO;
    const float* Osy = g_Oy + (size_t)(b * MD + kx) * MD * CO;
    for (int l = tid; l < 256; l += 256) {
        ((float4*)sOx)[l] = ((const float4*)Osx)[l];
        ((float4*)sOy)[l] = ((const float4*)Osy)[l];
    }
    __syncthreads();

    int oq = tid & 15;    // o = 4*oq (2 pairs)
    int hg = tid >> 4;    // h' = hb + 2*hg + j
    u64 reE[2][2]={{0,0},{0,0}}, imE[2][2]={{0,0},{0,0}};
    u64 reO[2][2]={{0,0},{0,0}}, imO[2][2]={{0,0},{0,0}};
#pragma unroll
    for (int ky = 0; ky < MD; ++ky) {
        ulonglong2 vx = *(const ulonglong2*)&sOx[ky * 64 + 4 * oq];
        ulonglong2 vy = *(const ulonglong2*)&sOy[ky * 64 + 4 * oq];
        u64 vy0n = vy.x ^ SGN2;
        u64 vy1n = vy.y ^ SGN2;
#pragma unroll
        for (int j = 0; j < 2; ++j) {
            int hl = hg * 2 + j;
            ulonglong2 t = sT[ky * 32 + hl];
            u64 cc = t.x, ss = t.y;
            if ((ky & 1) == 0) {
                reE[j][0] = fma2(vx.x, cc, reE[j][0]);  reE[j][0] = fma2(vy0n, ss, reE[j][0]);
                reE[j][1] = fma2(vx.y, cc, reE[j][1]);  reE[j][1] = fma2(vy1n, ss, reE[j][1]);
                imE[j][0] = fma2(vx.x, ss, imE[j][0]);  imE[j][0] = fma2(vy.x, cc, imE[j][0]);
                imE[j][1] = fma2(vx.y, ss, imE[j][1]);  imE[j][1] = fma2(vy.y, cc, imE[j][1]);
            } else {
                reO[j][0] = fma2(vx.x, cc, reO[j][0]);  reO[j][0] = fma2(vy0n, ss, reO[j][0]);
                reO[j][1] = fma2(vx.y, cc, reO[j][1]);  reO[j][1] = fma2(vy1n, ss, reO[j][1]);
                imO[j][0] = fma2(vx.x, ss, imO[j][0]);  imO[j][0] = fma2(vy.x, cc, imO[j][0]);
                imO[j][1] = fma2(vx.y, ss, imO[j][1]);  imO[j][1] = fma2(vy.y, cc, imO[j][1]);
            }
        }
    }
#pragma unroll
    for (int j = 0; j < 2; ++j) {
        int h = hb + hg * 2 + j;
        size_t b0 = ((size_t)(b * Hh + h     ) * MD + kx) * CO + 4 * oq;
        size_t b1 = ((size_t)(b * Hh + h + 64) * MD + kx) * CO + 4 * oq;
        *(u64*)&g_Gx[b0    ] = add2(reE[j][0], reO[j][0]);
        *(u64*)&g_Gx[b0 + 2] = add2(reE[j][1], reO[j][1]);
        *(u64*)&g_Gy[b0    ] = add2(imE[j][0], imO[j][0]);
        *(u64*)&g_Gy[b0 + 2] = add2(imE[j][1], imO[j][1]);
        *(u64*)&g_Gx[b1    ] = add2(reE[j][0], reO[j][0] ^ SGN2);
        *(u64*)&g_Gx[b1 + 2] = add2(reE[j][1], reO[j][1] ^ SGN2);
        *(u64*)&g_Gy[b1    ] = add2(imE[j][0], imO[j][0] ^ SGN2);
        *(u64*)&g_Gy[b1 + 2] = add2(imE[j][1], imO[j][1] ^ SGN2);
    }
}

// ============ stage E (radix-2, 128 threads): y[w'] = Se+So, y[w'+64] = Se-So ============
#define YPAD 66
__global__ void __launch_bounds__(128) stageE(float* __restrict__ y) {
    __shared__ __align__(16) float sGx[MD * CO];
    __shared__ __align__(16) float sGy[MD * CO];
    __shared__ __align__(16) float sY [Ww * YPAD];
    __shared__ __align__(16) u64 sEc[128];
    __shared__ __align__(16) u64 sEs[128];
    int b = blockIdx.x >> 7, h = blockIdx.x & 127;
    int tid = threadIdx.x;
    const float SC = 1.0f / 16384.0f;
    {
        float s, c;
        sincosf((float)tid * THETA, &s, &c);
        sEc[tid] = pk(2.0f * SC * c, 2.0f * SC * c);
        sEs[tid] = pk(-2.0f * SC * s, -2.0f * SC * s);
    }
    const float4* Gxs = (const float4*)&g_Gx[(size_t)(b * Hh + h) * MD * CO];
    const float4* Gys = (const float4*)&g_Gy[(size_t)(b * Hh + h) * MD * CO];
    for (int l = tid; l < MD * CO / 4; l += 128) {
        ((float4*)sGx)[l] = Gxs[l];
        ((float4*)sGy)[l] = Gys[l];
    }
    __syncthreads();
    int wl   = tid & 63;      // w' < 64
    int ohf  = tid >> 6;      // o-half
    u64 tc[16], ts[16];
    tc[0] = pk(SC, SC);  ts[0] = 0;
#pragma unroll
    for (int kx = 1; kx < MD; ++kx) {
        int idx = (kx * wl) & 127;
        tc[kx] = sEc[idx];
        ts[kx] = sEs[idx];
    }

#pragma unroll 2
    for (int oq = 0; oq < 8; ++oq) {
        int oc = (ohf * 8 + oq) * 4;     // o base (4 floats)
        u64 ae01 = 0, ae23 = 0, ao01 = 0, ao23 = 0;
#pragma unroll
        for (int kx = 0; kx < MD; ++kx) {
            ulonglong2 vx = *(const ulonglong2*)&sGx[kx * 64 + oc];
            ulonglong2 vy = *(const ulonglong2*)&sGy[kx * 64 + oc];
            if ((kx & 1) == 0) {
                ae01 = fma2(vx.x, tc[kx], ae01);  ae01 = fma2(vy.x, ts[kx], ae01);
                ae23 = fma2(vx.y, tc[kx], ae23);  ae23 = fma2(vy.y, ts[kx], ae23);
            } else {
                ao01 = fma2(vx.x, tc[kx], ao01);  ao01 = fma2(vy.x, ts[kx], ao01);
                ao23 = fma2(vx.y, tc[kx], ao23);  ao23 = fma2(vy.y, ts[kx], ao23);
            }
        }
        *(u64*)&sY[ wl       * YPAD + oc    ] = add2(ae01, ao01);
        *(u64*)&sY[ wl       * YPAD + oc + 2] = add2(ae23, ao23);
        *(u64*)&sY[(wl + 64) * YPAD + oc    ] = add2(ae01, ao01 ^ SGN2);
        *(u64*)&sY[(wl + 64) * YPAD + oc + 2] = add2(ae23, ao23 ^ SGN2);
    }
    __syncthreads();
    float* yb = y + (size_t)(b * Hh + h) * Ww * CO;
    for (int l = tid; l < Ww * CO / 2; l += 128) {
        int idx = l * 2;
        int ww = idx >> 6, o = idx & 63;
        *(u64*)&yb[idx] = *(const u64*)&sY[ww * YPAD + o];
    }
}

extern "C" void kernel_launch(void* const* d_in, const int* in_sizes, int n_in,
                              void* d_out, int out_size) {
    const float* x  = (const float*)d_in[0];
    const float* wr = (const float*)d_in[1];
    const float* wi = (const float*)d_in[2];
    float* y = (float*)d_out;

    fusedAT<<<2048, 256>>>(x, wr, wi);   // 1024 A-blocks + 1024 transpose blocks
    stageB<<<B * MD, 256>>>();
    stageC<<<MD * MD, 256>>>();
    stageD<<<B * MD * 2, 256>>>();
    stageE<<<B * Hh, 128>>>(y);
}